// round 6
// baseline (speedup 1.0000x reference)
#include <cuda_runtime.h>
#include <cuda_bf16.h>
#include <math.h>

// Problem constants (fixed by setup_inputs): B=8, T=200, U=100, V=512
#define B_  8
#define T_  200
#define U_  100
#define U1_ 101
#define V_  512

// Scratch (device globals — allocation-free rule)
__device__ float g_blank[B_ * T_ * U1_];   // log P(blank | b,t,u)
__device__ float g_emit [B_ * T_ * U_ ];   // log P(label[u] | b,t,u)
__device__ float g_costs[B_];

// ---------------------------------------------------------------------------
// Kernel 1: per-row log-softmax reduction over V=512.
// One warp per (b,t,u) row. Lane loads 4 float4 (16 floats). Extract
// blank_lp = x[0]-lse and emit_lp = x[label[u]]-lse.
// ---------------------------------------------------------------------------
__global__ __launch_bounds__(256, 8)
void lse_kernel(const float* __restrict__ acts,
                const int* __restrict__ labels)
{
    const int warps_per_block = blockDim.x >> 5;
    const int wid  = threadIdx.x >> 5;
    const int lane = threadIdx.x & 31;
    const int row  = blockIdx.x * warps_per_block + wid;   // 0 .. B*T*U1-1
    const int total_rows = B_ * T_ * U1_;
    if (row >= total_rows) return;

    const float4* rp = reinterpret_cast<const float4*>(acts + (size_t)row * V_);

    // 4 independent float4 loads per lane (MLP=4), 128 float4 per row
    float4 v0 = rp[lane +  0];
    float4 v1 = rp[lane + 32];
    float4 v2 = rp[lane + 64];
    float4 v3 = rp[lane + 96];

    float m = fmaxf(fmaxf(fmaxf(v0.x, v0.y), fmaxf(v0.z, v0.w)),
                    fmaxf(fmaxf(v1.x, v1.y), fmaxf(v1.z, v1.w)));
    m = fmaxf(m, fmaxf(fmaxf(fmaxf(v2.x, v2.y), fmaxf(v2.z, v2.w)),
                       fmaxf(fmaxf(v3.x, v3.y), fmaxf(v3.z, v3.w))));
    #pragma unroll
    for (int off = 16; off > 0; off >>= 1)
        m = fmaxf(m, __shfl_xor_sync(0xFFFFFFFFu, m, off));

    float s = __expf(v0.x - m) + __expf(v0.y - m) + __expf(v0.z - m) + __expf(v0.w - m)
            + __expf(v1.x - m) + __expf(v1.y - m) + __expf(v1.z - m) + __expf(v1.w - m)
            + __expf(v2.x - m) + __expf(v2.y - m) + __expf(v2.z - m) + __expf(v2.w - m)
            + __expf(v3.x - m) + __expf(v3.y - m) + __expf(v3.z - m) + __expf(v3.w - m);
    #pragma unroll
    for (int off = 16; off > 0; off >>= 1)
        s += __shfl_xor_sync(0xFFFFFFFFu, s, off);

    if (lane == 0) {
        const float lse = m + __logf(s);
        const int b = row / (T_ * U1_);
        const int r = row % (T_ * U1_);
        const int t = r / U1_;
        const int u = r % U1_;
        const float* rowp = acts + (size_t)row * V_;
        g_blank[row] = rowp[0] - lse;            // BLANK = index 0 (L1-hot)
        if (u < U_) {
            int lab = labels[b * U_ + u];
            lab = min(max(lab, 0), V_ - 1);      // defensive clamp (no-op when dtype right)
            g_emit[(b * T_ + t) * U_ + u] = rowp[lab] - lse;
        }
    }
}

// ---------------------------------------------------------------------------
// Kernel 2: per-batch alpha recursion via anti-diagonal wavefront.
// Both deps of diag d live on diag d-1. blank/emit staged in SMEM (162 KB).
// ---------------------------------------------------------------------------
#define SM_BLANK_F (T_ * U1_)            // 20200 floats
#define SM_EMIT_F  (T_ * U_)             // 20000 floats
#define SM_DIAG_F  (2 * (T_ + 8))
#define SM2_BYTES  ((SM_BLANK_F + SM_EMIT_F + SM_DIAG_F) * (int)sizeof(float))

__device__ __forceinline__ float logaddf(float a, float b) {
    float hi = fmaxf(a, b);
    float lo = fminf(a, b);
    // __expf(-inf) -> 0, log1pf(0) -> 0: exact passthrough of the finite arm
    return hi + log1pf(__expf(lo - hi));
}

__global__ void alpha_kernel(const int* __restrict__ act_lens,
                             const int* __restrict__ label_lens)
{
    extern __shared__ float sm[];
    float* blank_s = sm;                        // [t*U1 + u]
    float* emit_s  = sm + SM_BLANK_F;           // [t*U  + u]
    float* dA      = sm + SM_BLANK_F + SM_EMIT_F;
    float* dB      = dA + (T_ + 8);

    const int b  = blockIdx.x;
    const int Tb = act_lens[b];
    const int Ub = label_lens[b];

    // Stage tables (coalesced)
    const float* gb = g_blank + b * T_ * U1_;
    const float* ge = g_emit  + b * T_ * U_;
    const int nb = Tb * U1_;
    const int ne = Tb * U_;
    for (int i = threadIdx.x; i < nb; i += blockDim.x) blank_s[i] = gb[i];
    for (int i = threadIdx.x; i < ne; i += blockDim.x) emit_s[i]  = ge[i];
    __syncthreads();

    float* cur = dA;
    float* prev = dB;
    const int ndiag = Tb + Ub;                  // d = 0 .. Tb-1+Ub
    for (int d = 0; d < ndiag; ++d) {
        const int tlo = max(0, d - Ub);
        const int thi = min(d, Tb - 1);
        for (int t = tlo + (int)threadIdx.x; t <= thi; t += blockDim.x) {
            const int u = d - t;
            float val;
            if (d == 0) {
                val = 0.0f;
            } else {
                float v1 = -INFINITY, v2 = -INFINITY;
                if (t > 0) v1 = prev[t - 1] + blank_s[(t - 1) * U1_ + u];
                if (u > 0) v2 = prev[t]     + emit_s [t * U_ + (u - 1)];
                val = logaddf(v1, v2);
            }
            cur[t] = val;
        }
        __syncthreads();
        float* tmp = cur; cur = prev; prev = tmp;
    }
    // prev holds the last diagonal (d = Tb-1+Ub); alpha[Tb-1, Ub] = prev[Tb-1]
    if (threadIdx.x == 0) {
        const float ll = prev[Tb - 1] + blank_s[(Tb - 1) * U1_ + Ub];
        g_costs[b] = -ll;
    }
}

// ---------------------------------------------------------------------------
// Kernel 3: deterministic batch-sum into d_out (which is poison-initialized)
// ---------------------------------------------------------------------------
__global__ void sum_kernel(float* __restrict__ out)
{
    if (threadIdx.x == 0) {
        float s = 0.0f;
        #pragma unroll
        for (int i = 0; i < B_; ++i) s += g_costs[i];
        out[0] = s;
    }
}

extern "C" void kernel_launch(void* const* d_in, const int* in_sizes, int n_in,
                              void* d_out, int out_size)
{
    const float* acts       = (const float*)d_in[0];
    const int*   labels     = (const int*)d_in[1];   // int32 (JAX x64 disabled)
    const int*   act_lens   = (const int*)d_in[2];
    const int*   label_lens = (const int*)d_in[3];
    float*       out        = (float*)d_out;

    // Opt-in to 162 KB dynamic SMEM for the alpha kernel (host-side attribute,
    // not a stream op; safe under graph capture).
    (void)cudaFuncSetAttribute(alpha_kernel,
                               cudaFuncAttributeMaxDynamicSharedMemorySize,
                               SM2_BYTES);

    // Kernel 1: B*T*U1 = 161600 rows, 8 warps/block -> 20200 blocks
    const int rows = B_ * T_ * U1_;
    const int wpb = 8;
    lse_kernel<<<(rows + wpb - 1) / wpb, wpb * 32>>>(acts, labels);

    // Kernel 2: one block per batch element
    alpha_kernel<<<B_, 256, SM2_BYTES>>>(act_lens, label_lens);

    // Kernel 3: final reduction
    sum_kernel<<<1, 32>>>(out);
}

// round 8
// speedup vs baseline: 1.8503x; 1.8503x over previous
#include <cuda_runtime.h>
#include <cuda_bf16.h>
#include <math.h>

// Problem constants (fixed by setup_inputs): B=8, T=200, U=100, V=512
#define B_   8
#define T_   200
#define U_   100
#define U1_  101
#define V_   512
#define RSTR 102            // padded row stride for blank/emit tables (conflict-free on diagonals)
#define NEG  (-1.0e30f)     // effective -inf without NaN hazards

// Scratch (device globals — allocation-free rule)
__device__ float g_blank[B_ * T_ * RSTR];  // log P(blank | b,t,u),  [b][t*102+u], u in [0,100]
__device__ float g_emit [B_ * T_ * RSTR];  // log P(label[u]|b,t,u), [b][t*102+u], u in [0,99]
__device__ float g_costs[B_];
__device__ unsigned g_done = 0;

// ---------------------------------------------------------------------------
// Kernel 1: per-row log-softmax reduction over V=512. One warp per (b,t,u).
// ---------------------------------------------------------------------------
__global__ __launch_bounds__(256, 8)
void lse_kernel(const float* __restrict__ acts,
                const int* __restrict__ labels)
{
    const int wid  = threadIdx.x >> 5;
    const int lane = threadIdx.x & 31;
    const int row  = blockIdx.x * (blockDim.x >> 5) + wid;   // 0 .. B*T*U1-1
    if (row >= B_ * T_ * U1_) return;

    const float4* rp = reinterpret_cast<const float4*>(acts + (size_t)row * V_);
    float4 v0 = rp[lane +  0];
    float4 v1 = rp[lane + 32];
    float4 v2 = rp[lane + 64];
    float4 v3 = rp[lane + 96];

    float m = fmaxf(fmaxf(fmaxf(v0.x, v0.y), fmaxf(v0.z, v0.w)),
                    fmaxf(fmaxf(v1.x, v1.y), fmaxf(v1.z, v1.w)));
    m = fmaxf(m, fmaxf(fmaxf(fmaxf(v2.x, v2.y), fmaxf(v2.z, v2.w)),
                       fmaxf(fmaxf(v3.x, v3.y), fmaxf(v3.z, v3.w))));
    #pragma unroll
    for (int off = 16; off > 0; off >>= 1)
        m = fmaxf(m, __shfl_xor_sync(0xFFFFFFFFu, m, off));

    float s = __expf(v0.x - m) + __expf(v0.y - m) + __expf(v0.z - m) + __expf(v0.w - m)
            + __expf(v1.x - m) + __expf(v1.y - m) + __expf(v1.z - m) + __expf(v1.w - m)
            + __expf(v2.x - m) + __expf(v2.y - m) + __expf(v2.z - m) + __expf(v2.w - m)
            + __expf(v3.x - m) + __expf(v3.y - m) + __expf(v3.z - m) + __expf(v3.w - m);
    #pragma unroll
    for (int off = 16; off > 0; off >>= 1)
        s += __shfl_xor_sync(0xFFFFFFFFu, s, off);

    if (lane == 0) {
        const float lse = m + __logf(s);
        const int b = row / (T_ * U1_);
        const int r = row % (T_ * U1_);
        const int t = r / U1_;
        const int u = r % U1_;
        const float* rowp = acts + (size_t)row * V_;
        const int base = (b * T_ + t) * RSTR + u;
        g_blank[base] = v0.x - lse;              // acts[row][0], already in register (lane 0)
        if (u < U_) {
            int lab = labels[b * U_ + u];
            lab = min(max(lab, 0), V_ - 1);
            g_emit[base] = rowp[lab] - lse;
        }
    }
}

// ---------------------------------------------------------------------------
// Kernel 2: register-resident anti-diagonal wavefront with warp halo.
// Thread (w, lane) owns row t = 24*w + lane (8 warps, 8-row overlap = 200 rows).
// alpha lives in a register; t-1 dependency travels via shfl_up; one smem
// exchange + barrier every 8 steps refreshes the 8 halo lanes.
//   alpha[t,u] = logadd(alpha[t-1,u] + blank[t-1,u], alpha[t,u-1] + emit[t,u-1])
// ---------------------------------------------------------------------------
#define SM_TAB_F (T_ * RSTR)     // 20400 floats per table
#define SM2_BYTES ((2 * SM_TAB_F + 2 * (T_ + 8) + 16) * (int)sizeof(float))

__global__ __launch_bounds__(256, 1)
void alpha_kernel(const int* __restrict__ act_lens,
                  const int* __restrict__ label_lens,
                  float* __restrict__ out)
{
    extern __shared__ float sm[];
    float* blank_s = sm;                         // [t*102 + u]
    float* emit_s  = sm + SM_TAB_F;              // [t*102 + u]
    float* row_a   = sm + 2 * SM_TAB_F;          // [2][T_+8] double-buffered exchange
    float* cost_sh = row_a + 2 * (T_ + 8);

    const int b    = blockIdx.x;
    const int Tb   = act_lens[b];
    const int Ub   = label_lens[b];
    const int tid  = threadIdx.x;
    const int w    = tid >> 5;
    const int lane = tid & 31;
    const int t    = 24 * w + lane;              // 0..199, rows overlap by 8 between warps

    // Stage tables (global layout == smem layout, stride 102; float4 copy)
    {
        const float4* gb4 = reinterpret_cast<const float4*>(g_blank + b * T_ * RSTR);
        const float4* ge4 = reinterpret_cast<const float4*>(g_emit  + b * T_ * RSTR);
        float4* bs4 = reinterpret_cast<float4*>(blank_s);
        float4* es4 = reinterpret_cast<float4*>(emit_s);
        const int n4 = (Tb * RSTR + 3) >> 2;     // Tb*102 is even; round up safe (array padded)
        for (int i = tid; i < n4; i += blockDim.x) { bs4[i] = gb4[i]; es4[i] = ge4[i]; }
    }
    __syncthreads();

    const float* my_blank = blank_s + t * RSTR;
    const float* my_emit  = emit_s  + t * RSTR;

    float a = NEG;
    int   u_old = -1 - t;                        // u before step d: u_old = d-1-t
    const int ndiag   = Tb + Ub;                 // d = 0..ndiag-1
    const int ngroups = (ndiag + 7) >> 3;
    int parity = 0;

    for (int g = 0; g < ngroups; ++g) {
        #pragma unroll
        for (int k = 0; k < 8; ++k) {
            // blank/emit reads: clamped index (masked cells don't care)
            const int ci  = min(max(u_old, 0), 100);
            const float bl = my_blank[ci];
            const float em = my_emit[min(ci, 99)];

            const float s = a + bl;              // sender value: alpha(t,u_old)+blank(t,u_old)
            float r = __shfl_up_sync(0xFFFFFFFFu, s, 1);
            if (lane == 0) r = NEG;              // w==0: no t-1; w>0: halo lane (stale by design)
            const float v2 = a + em;

            const float hi = fmaxf(r, v2);
            const float lo = fminf(r, v2);
            const float val = hi + __logf(1.0f + __expf(lo - hi));

            const int u_new = u_old + 1;         // = d - t
            a = (u_new >= 0 && u_new <= Ub) ? val : NEG;
            if (t == 0 && u_new == 0) a = 0.0f;  // alpha[0,0] = 0 (only at d==0)

            // capture final cell: alpha(Tb-1, Ub) + blank(Tb-1, Ub)
            if (u_new == Ub && t == Tb - 1 && (w == 0 || lane > k))
                *cost_sh = -(a + my_blank[Ub]);

            ++u_old;
        }
        // halo refresh: rows are exactly partitioned among {w==0 all lanes} ∪ {w>0, lane>=8}
        if (w == 0 || lane >= 8) row_a[parity * (T_ + 8) + t] = a;
        __syncthreads();
        if (w > 0 && lane < 8) a = row_a[parity * (T_ + 8) + t];
        parity ^= 1;
    }

    __syncthreads();
    if (tid == 0) {
        g_costs[b] = *cost_sh;
        __threadfence();
        const unsigned r = atomicAdd(&g_done, 1u);
        if (r == B_ - 1) {                       // last block: deterministic final sum
            __threadfence();
            float ssum = 0.0f;
            #pragma unroll
            for (int i = 0; i < B_; ++i) ssum += g_costs[i];
            out[0] = ssum;
            g_done = 0;                          // reset for next graph replay
        }
    }
}

extern "C" void kernel_launch(void* const* d_in, const int* in_sizes, int n_in,
                              void* d_out, int out_size)
{
    const float* acts       = (const float*)d_in[0];
    const int*   labels     = (const int*)d_in[1];   // int32 (JAX x64 disabled)
    const int*   act_lens   = (const int*)d_in[2];
    const int*   label_lens = (const int*)d_in[3];
    float*       out        = (float*)d_out;

    (void)cudaFuncSetAttribute(alpha_kernel,
                               cudaFuncAttributeMaxDynamicSharedMemorySize,
                               SM2_BYTES);

    const int rows = B_ * T_ * U1_;
    const int wpb  = 8;
    lse_kernel<<<(rows + wpb - 1) / wpb, wpb * 32>>>(acts, labels);

    alpha_kernel<<<B_, 256, SM2_BYTES>>>(act_lens, label_lens, out);
}